// round 15
// baseline (speedup 1.0000x reference)
#include <cuda_runtime.h>
#include <cstddef>
#include <cstdint>

#define SQ    2048
#define HIDD  2048
#define NHQ   16
#define NKVH  4
#define HDIM  128
#define QKVN  3072
#define QSCALE 0.08838834764831845f
#define RMSEPS 1e-6f

#define ATTN_N ((size_t)SQ * NHQ * HDIM)     // 4.19M elements

// ---------------------------------------------------------------------------
// Scratch (static device globals; allocation is forbidden)
// ---------------------------------------------------------------------------
__device__ float g_qkv   [(size_t)SQ * QKVN];
__device__ float g_q     [(size_t)SQ * NHQ * HDIM];     // tf32-rounded
__device__ float g_k     [(size_t)SQ * NKVH * HDIM];    // tf32-rounded
__device__ float g_vT    [(size_t)NKVH * HDIM * SQ];    // V^T, tf32-rounded
__device__ float g_scores[(size_t)NHQ * SQ * SQ];       // scores -> probs (tf32)
__device__ float g_attn  [ATTN_N];                      // tf32-rounded
__device__ float g_pvp   [4 * ATTN_N];                  // PV k-chunk partials
__device__ float g_hhi   [(size_t)SQ * HIDD];           // hidden, tf32-rounded
__device__ float g_whi   [(size_t)QKVN * HIDD];         // wqkv, tf32-rounded
__device__ float g_wot   [(size_t)HIDD * HIDD];         // wo tf32-rounded

// ---------------------------------------------------------------------------
// Helpers
// ---------------------------------------------------------------------------
__device__ __forceinline__ float tf32r(float x) {
    unsigned u;
    asm("cvt.rna.tf32.f32 %0, %1;" : "=r"(u) : "f"(x));
    return __uint_as_float(u);
}

__device__ __forceinline__ void cp16(uint32_t dst, const float* src) {
    asm volatile("cp.async.cg.shared.global [%0], [%1], 16;\n" :: "r"(dst), "l"(src));
}

__device__ __forceinline__ void ldm4(uint32_t* r, uint32_t addr) {
    asm volatile("ldmatrix.sync.aligned.m8n8.x4.shared.b16 {%0,%1,%2,%3}, [%4];\n"
                 : "=r"(r[0]), "=r"(r[1]), "=r"(r[2]), "=r"(r[3]) : "r"(addr));
}

__device__ __forceinline__ void mma8(float* c, const uint32_t* a,
                                     uint32_t b0, uint32_t b1) {
    asm volatile(
        "mma.sync.aligned.m16n8k8.row.col.f32.tf32.tf32.f32 "
        "{%0,%1,%2,%3}, {%4,%5,%6,%7}, {%8,%9}, {%0,%1,%2,%3};\n"
        : "+f"(c[0]), "+f"(c[1]), "+f"(c[2]), "+f"(c[3])
        : "r"(a[0]), "r"(a[1]), "r"(a[2]), "r"(a[3]), "r"(b0), "r"(b1));
}

#define SST    36                       // smem row stride (floats)
#define STAGEF (128 * SST)              // floats per matrix per stage
#define CHKB   (STAGEF * 4)             // bytes per 128x32 chunk buffer (18432)
#define SSTB   (2 * CHKB)               // bytes per stage (A+B)
#define GSMEM  (3 * SSTB)               // 110592 B (also = 4 B-chunks + 2 A-bufs)

// ---------------------------------------------------------------------------
// tf32 GEMM core: C = A * B^T (+bias)(tf32 out), 128x128x32 tiles,
// 3-stage cp.async, single barrier per k-tile.
// ---------------------------------------------------------------------------
__device__ __forceinline__ void cp_stage(const float* Ag, const float* Bg,
                                         int lda, int ldb,
                                         uint32_t dA, uint32_t dB) {
#pragma unroll
    for (int i = 0; i < 4; i++) {
        cp16(dA + i * 32 * SST * 4, Ag + (size_t)(i * 32) * lda);
        cp16(dB + i * 32 * SST * 4, Bg + (size_t)(i * 32) * ldb);
    }
}

__device__ __forceinline__ void gemm_core(
    const float* __restrict__ A, int lda,
    const float* __restrict__ B, int ldb,
    float* __restrict__ C, int ldc,
    int K, const float* __restrict__ bias,
    int cvt, int bx, int by)
{
    extern __shared__ float dsm[];
    const int tid  = threadIdx.x;
    const int wid  = tid >> 5, lane = tid & 31;
    const int wm   = (wid & 1) * 64, wn = (wid >> 1) * 32;
    const int ldrw = tid >> 3, ldcl = (tid & 7) * 4;

    const uint32_t sb = (uint32_t)__cvta_generic_to_shared(dsm);
    const float* Ag = A + (size_t)(by * 128 + ldrw) * lda + ldcl;
    const float* Bg = B + (size_t)(bx * 128 + ldrw) * ldb + ldcl;
    const uint32_t dA0 = sb + (ldrw * SST + ldcl) * 4;

    const int nK = K >> 5;

    float acc[4][4][4];
#pragma unroll
    for (int a = 0; a < 4; a++)
#pragma unroll
        for (int b = 0; b < 4; b++)
#pragma unroll
            for (int c = 0; c < 4; c++) acc[a][b][c] = 0.f;

    const int mi  = lane >> 3, l7 = lane & 7;
    const int aro = (mi & 1) * 8 + l7, aco = (mi >> 1) * 4;
    const int bro = (mi >> 1) * 8 + l7, bco = (mi & 1) * 4;

    cp_stage(Ag, Bg, lda, ldb, dA0, dA0 + CHKB);
    asm volatile("cp.async.commit_group;\n");
    if (nK > 1)
        cp_stage(Ag + 32, Bg + 32, lda, ldb, dA0 + SSTB, dA0 + SSTB + CHKB);
    asm volatile("cp.async.commit_group;\n");

    for (int kt = 0; kt < nK; kt++) {
        asm volatile("cp.async.wait_group 1;\n");
        __syncthreads();

        if (kt + 2 < nK) {
            const int sti = (kt + 2) % 3;
            cp_stage(Ag + (kt + 2) * 32, Bg + (kt + 2) * 32, lda, ldb,
                     dA0 + sti * SSTB, dA0 + sti * SSTB + CHKB);
        }
        asm volatile("cp.async.commit_group;\n");

        const uint32_t sA = sb + (kt % 3) * SSTB;
        const uint32_t sB = sA + CHKB;
#pragma unroll
        for (int k = 0; k < 32; k += 8) {
            uint32_t bq[8];
            ldm4(bq,     sB + ((wn +      bro) * SST + k + bco) * 4);
            ldm4(bq + 4, sB + ((wn + 16 + bro) * SST + k + bco) * 4);
#pragma unroll
            for (int mt = 0; mt < 4; mt++) {
                uint32_t aq[4];
                ldm4(aq, sA + ((wm + 16 * mt + aro) * SST + k + aco) * 4);
                mma8(acc[mt][0], aq, bq[0], bq[1]);
                mma8(acc[mt][1], aq, bq[2], bq[3]);
                mma8(acc[mt][2], aq, bq[4], bq[5]);
                mma8(acc[mt][3], aq, bq[6], bq[7]);
            }
        }
    }

    const int g = lane >> 2, tg = lane & 3;
#pragma unroll
    for (int mt = 0; mt < 4; mt++) {
#pragma unroll
        for (int nt = 0; nt < 4; nt++) {
            const int r0 = by * 128 + wm + 16 * mt + g;
            const int c0 = bx * 128 + wn + 8 * nt + tg * 2;
            float x0 = acc[mt][nt][0], x1 = acc[mt][nt][1];
            float x2 = acc[mt][nt][2], x3 = acc[mt][nt][3];
            if (bias) {
                float b0 = bias[c0], b1 = bias[c0 + 1];
                x0 += b0; x1 += b1; x2 += b0; x3 += b1;
            }
            if (cvt) { x0 = tf32r(x0); x1 = tf32r(x1); x2 = tf32r(x2); x3 = tf32r(x3); }
            *reinterpret_cast<float2*>(C + (size_t)r0 * ldc + c0) = make_float2(x0, x1);
            *reinterpret_cast<float2*>(C + (size_t)(r0 + 8) * ldc + c0) = make_float2(x2, x3);
        }
    }
}

// ---------------------------------------------------------------------------
// GEMM kernels
// ---------------------------------------------------------------------------
__global__ void __launch_bounds__(256, 2) k_qkv(const float* __restrict__ bias) {
    gemm_core(g_hhi, HIDD, g_whi, HIDD, g_qkv, QKVN, HIDD, bias, 0,
              blockIdx.x, blockIdx.y);
}

// ---------------------------------------------------------------------------
// Scores, 4 q-heads of one GQA group per CTA. The K tile (128x128) is loaded
// ONCE into 4 resident smem chunks; A (q) streams through 2 buffers; the 16
// (head, chunk) jobs run back-to-back, amortizing prologue/epilogue 4x.
// smem: 4 B-chunks + 2 A-buffers = 6 * 18432 = 110592 B.
// ---------------------------------------------------------------------------
__global__ void __launch_bounds__(256, 2) k_scores4()
{
    const int bx = blockIdx.x, by = blockIdx.y, kvh = blockIdx.z;
    if (bx > by) return;   // tile entirely above causal diagonal
    extern __shared__ float dsm[];
    const int tid  = threadIdx.x;
    const int wid  = tid >> 5, lane = tid & 31;
    const int wm   = (wid & 1) * 64, wn = (wid >> 1) * 32;
    const int ldrw = tid >> 3, ldcl = (tid & 7) * 4;

    const uint32_t sb = (uint32_t)__cvta_generic_to_shared(dsm);
    const uint32_t Bs = sb;                    // 4 resident B chunks
    const uint32_t As = sb + 4 * CHKB;         // 2 A buffers
    const uint32_t dB0 = Bs + (ldrw * SST + ldcl) * 4;
    const uint32_t dA0 = As + (ldrw * SST + ldcl) * 4;

    const float* Bg  = g_k + (size_t)(bx * 128 + ldrw) * (NKVH * HDIM)
                     + kvh * HDIM + ldcl;
    const float* Ag0 = g_q + (size_t)(by * 128 + ldrw) * (NHQ * HDIM)
                     + kvh * 4 * HDIM + ldcl;

    // Load the whole K tile (4 chunks) + head0 chunk0 of A, one commit group.
#pragma unroll
    for (int c = 0; c < 4; c++)
#pragma unroll
        for (int i = 0; i < 4; i++)
            cp16(dB0 + c * CHKB + i * 32 * SST * 4,
                 Bg + (size_t)(i * 32) * (NKVH * HDIM) + c * 32);
#pragma unroll
    for (int i = 0; i < 4; i++)
        cp16(dA0 + i * 32 * SST * 4, Ag0 + (size_t)(i * 32) * (NHQ * HDIM));
    asm volatile("cp.async.commit_group;\n");

    const int mi  = lane >> 3, l7 = lane & 7;
    const int aro = (mi & 1) * 8 + l7, aco = (mi >> 1) * 4;
    const int bro = (mi >> 1) * 8 + l7, bco = (mi & 1) * 4;
    const int g = lane >> 2, tg = lane & 3;

    float acc[4][4][4];
#pragma unroll
    for (int a = 0; a < 4; a++)
#pragma unroll
        for (int b = 0; b < 4; b++)
#pragma unroll
            for (int c = 0; c < 4; c++) acc[a][b][c] = 0.f;

    for (int t = 0; t < 16; t++) {          // t = head*4 + chunk
        if (t + 1 < 16) {
            const int qh = (t + 1) >> 2, c = (t + 1) & 3;
            const float* Ag = Ag0 + qh * HDIM + c * 32;
#pragma unroll
            for (int i = 0; i < 4; i++)
                cp16(dA0 + ((t + 1) & 1) * CHKB + i * 32 * SST * 4,
                     Ag + (size_t)(i * 32) * (NHQ * HDIM));
            asm volatile("cp.async.commit_group;\n");
            asm volatile("cp.async.wait_group 1;\n");
        } else {
            asm volatile("cp.async.wait_group 0;\n");
        }
        __syncthreads();

        const uint32_t sA = As + (t & 1) * CHKB;
        const uint32_t sB = Bs + (t & 3) * CHKB;
#pragma unroll
        for (int k = 0; k < 32; k += 8) {
            uint32_t bq[8];
            ldm4(bq,     sB + ((wn +      bro) * SST + k + bco) * 4);
            ldm4(bq + 4, sB + ((wn + 16 + bro) * SST + k + bco) * 4);
#pragma unroll
            for (int mt = 0; mt < 4; mt++) {
                uint32_t aq[4];
                ldm4(aq, sA + ((wm + 16 * mt + aro) * SST + k + aco) * 4);
                mma8(acc[mt][0], aq, bq[0], bq[1]);
                mma8(acc[mt][1], aq, bq[2], bq[3]);
                mma8(acc[mt][2], aq, bq[4], bq[5]);
                mma8(acc[mt][3], aq, bq[6], bq[7]);
            }
        }
        __syncthreads();   // A buffer (t&1) is reloaded at iteration t+1

        if ((t & 3) == 3) {  // head finished: write tile, reset accumulators
            const int h = kvh * 4 + (t >> 2);
            float* C = g_scores + (size_t)h * SQ * SQ;
#pragma unroll
            for (int mt = 0; mt < 4; mt++)
#pragma unroll
                for (int nt = 0; nt < 4; nt++) {
                    const int r0 = by * 128 + wm + 16 * mt + g;
                    const int c0 = bx * 128 + wn + 8 * nt + tg * 2;
                    *reinterpret_cast<float2*>(C + (size_t)r0 * SQ + c0) =
                        make_float2(acc[mt][nt][0], acc[mt][nt][1]);
                    *reinterpret_cast<float2*>(C + (size_t)(r0 + 8) * SQ + c0) =
                        make_float2(acc[mt][nt][2], acc[mt][nt][3]);
                    acc[mt][nt][0] = acc[mt][nt][1] = 0.f;
                    acc[mt][nt][2] = acc[mt][nt][3] = 0.f;
                }
        }
    }
}

// PV split along K into 512-wide chunks -> fp32 partials in g_pvp
__global__ void __launch_bounds__(256, 2) k_pv() {
    const int x = blockIdx.x, by = blockIdx.y, h = blockIdx.z;
    const int kmax = (by + 1) * 128;     // p[s,t]=0 for t>s (tile-aligned)
    const int k0 = x * 512;
    if (k0 >= kmax) return;
    const int len = min(512, kmax - k0);
    gemm_core(g_scores + (size_t)h * SQ * SQ + k0, SQ,
              g_vT + (size_t)(h >> 2) * HDIM * SQ + k0, SQ,
              g_pvp + (size_t)x * ATTN_N + h * HDIM, NHQ * HDIM,
              len, nullptr, 0, 0, by);
}
// Sum the per-row chunk count and tf32-round into g_attn
__global__ void __launch_bounds__(256) k_pv_reduce() {
    size_t i = (size_t)blockIdx.x * 256 + threadIdx.x;
    if (i >= ATTN_N) return;
    const int s  = (int)(i >> 11);          // / (NHQ*HDIM)
    const int nc = (s >> 9) + 1;            // chunks covering this row
    float v = g_pvp[i];
    if (nc > 1) v += g_pvp[ATTN_N + i];
    if (nc > 2) v += g_pvp[2 * ATTN_N + i];
    if (nc > 3) v += g_pvp[3 * ATTN_N + i];
    g_attn[i] = tf32r(v);
}
__global__ void __launch_bounds__(256, 2) k_out(const float* __restrict__ bo,
                                                float* __restrict__ out) {
    gemm_core(g_attn, NHQ * HDIM, g_wot, HIDD, out, HIDD, HIDD, bo, 0,
              blockIdx.x, blockIdx.y);
}

// ---------------------------------------------------------------------------
// tf32 prep kernels
// ---------------------------------------------------------------------------
__global__ void __launch_bounds__(256) k_round_h(const float* __restrict__ x) {
    int i = blockIdx.x * 256 + threadIdx.x;
    if (i < SQ * HIDD) g_hhi[i] = tf32r(x[i]);
}
__global__ void __launch_bounds__(256) k_cvt_w(const float* __restrict__ x) {
    int i = blockIdx.x * 256 + threadIdx.x;
    if (i < QKVN * HIDD) g_whi[i] = tf32r(x[i]);
}
__global__ void __launch_bounds__(256) k_cvt_wo(const float* __restrict__ x) {
    int i = blockIdx.x * 256 + threadIdx.x;
    if (i < HIDD * HIDD) g_wot[i] = tf32r(x[i]);
}

// V transpose: g_vT[c][s] = tf32(g_qkv[s][2560 + c]),  c in [0, 512)
__global__ void __launch_bounds__(256) k_vT() {
    __shared__ float t[32][33];
    const int c0 = blockIdx.x * 32, s0 = blockIdx.y * 32;
    const int tx = threadIdx.x, ty = threadIdx.y;  // 32 x 8
#pragma unroll
    for (int j = 0; j < 32; j += 8)
        t[ty + j][tx] = g_qkv[(size_t)(s0 + ty + j) * QKVN
                              + (NHQ + NKVH) * HDIM + c0 + tx];
    __syncthreads();
#pragma unroll
    for (int j = 0; j < 32; j += 8)
        g_vT[(size_t)(c0 + ty + j) * SQ + s0 + tx] = tf32r(t[tx][ty + j]);
}

// ---------------------------------------------------------------------------
// RMSNorm + RoPE (+q scaling), outputs tf32-rounded. grid (S, 20), 128 thr.
// ---------------------------------------------------------------------------
__global__ void __launch_bounds__(128) k_norm_rope(
    const float* __restrict__ cosb, const float* __restrict__ sinb,
    const float* __restrict__ qw,   const float* __restrict__ kw)
{
    const int s  = blockIdx.x;
    const int hh = blockIdx.y;
    const int d  = threadIdx.x;
    const float* row = g_qkv + (size_t)s * QKVN;

    const bool isq = (hh < 16);
    const int off = isq ? hh * HDIM : NHQ * HDIM + (hh - 16) * HDIM;
    float x = row[off + d];

    float sq = x * x;
#pragma unroll
    for (int o = 16; o; o >>= 1) sq += __shfl_xor_sync(0xffffffffu, sq, o);
    __shared__ float ws[4];
    __shared__ float rinv;
    if ((d & 31) == 0) ws[d >> 5] = sq;
    __syncthreads();
    if (d == 0)
        rinv = rsqrtf((ws[0] + ws[1] + ws[2] + ws[3]) * (1.0f / 128.0f) + RMSEPS);
    __syncthreads();

    const float w = isq ? qw[d] : kw[d];
    float xn = x * rinv * w;

    __shared__ float xs[128];
    xs[d] = xn;
    __syncthreads();

    const int j = d & 63;
    const float c  = cosb[(size_t)s * 64 + j];
    const float sn = sinb[(size_t)s * 64 + j];
    float o;
    if (d < 64) o = xs[d] * c - xs[d + 64] * sn;
    else        o = xs[j] * sn + xs[j + 64] * c;

    if (isq)
        g_q[(size_t)s * (NHQ * HDIM) + hh * HDIM + d] = tf32r(o * QSCALE);
    else
        g_k[(size_t)s * (NKVH * HDIM) + (hh - 16) * HDIM + d] = tf32r(o);
}

// ---------------------------------------------------------------------------
// Online causal softmax: fused max+sum pass, then exp+normalize pass.
// Writes tf32 probs; zeros only to the 128-aligned tile edge.
// ---------------------------------------------------------------------------
__global__ void __launch_bounds__(256) k_softmax()
{
    const int s = blockIdx.x, h = blockIdx.y;
    float* row = g_scores + ((size_t)h * SQ + s) * SQ;
    const int n = s + 1;
    const int kmax = ((s >> 7) + 1) << 7;
    const int tid = threadIdx.x;
    const int lane = tid & 31, w = tid >> 5;

    float m = -3.4e38f, ssum = 0.f;
    for (int t = tid; t < n; t += 256) {
        float x = row[t];
        float nm = fmaxf(m, x);
        ssum = ssum * expf(m - nm) + expf(x - nm);
        m = nm;
    }
#pragma unroll
    for (int o = 16; o; o >>= 1) {
        float om = __shfl_xor_sync(0xffffffffu, m, o);
        float os = __shfl_xor_sync(0xffffffffu, ssum, o);
        float nm = fmaxf(m, om);
        ssum = ssum * expf(m - nm) + os * expf(om - nm);
        m = nm;
    }
    __shared__ float sm[8], ss[8];
    if (lane == 0) { sm[w] = m; ss[w] = ssum; }
    __syncthreads();
    float M = sm[0], S = ss[0];
#pragma unroll
    for (int i = 1; i < 8; i++) {
        float nm = fmaxf(M, sm[i]);
        S = S * expf(M - nm) + ss[i] * expf(sm[i] - nm);
        M = nm;
    }
    const float inv = 1.0f / S;

    for (int t = tid; t < kmax; t += 256)
        row[t] = (t < n) ? tf32r(expf(row[t] - M) * inv) : 0.f;
}

// ---------------------------------------------------------------------------
// Launch
// ---------------------------------------------------------------------------
extern "C" void kernel_launch(void* const* d_in, const int* in_sizes, int n_in,
                              void* d_out, int out_size)
{
    const float* hidden = (const float*)d_in[0];
    const float* cosb   = (const float*)d_in[1];
    const float* sinb   = (const float*)d_in[2];
    const float* wqkv   = (const float*)d_in[6];
    const float* bqkv   = (const float*)d_in[7];
    const float* wo     = (const float*)d_in[8];
    const float* bo     = (const float*)d_in[9];
    const float* qw     = (const float*)d_in[10];
    const float* kw     = (const float*)d_in[11];
    float* out = (float*)d_out;

    cudaFuncSetAttribute(k_qkv,     cudaFuncAttributeMaxDynamicSharedMemorySize, GSMEM);
    cudaFuncSetAttribute(k_scores4, cudaFuncAttributeMaxDynamicSharedMemorySize, GSMEM);
    cudaFuncSetAttribute(k_pv,      cudaFuncAttributeMaxDynamicSharedMemorySize, GSMEM);
    cudaFuncSetAttribute(k_out,     cudaFuncAttributeMaxDynamicSharedMemorySize, GSMEM);

    // tf32 prep (single-rounded operands)
    k_round_h<<<(SQ * HIDD + 255) / 256, 256>>>(hidden);
    k_cvt_w<<<(QKVN * HIDD + 255) / 256, 256>>>(wqkv);
    k_cvt_wo<<<(HIDD * HIDD + 255) / 256, 256>>>(wo);

    // QKV single-pass tf32 GEMM
    k_qkv<<<dim3(QKVN / 128, SQ / 128), 256, GSMEM>>>(bqkv);

    // RMSNorm + RoPE (+scale) -> tf32 q/k; V transposed -> tf32 vT
    k_norm_rope<<<dim3(SQ, NHQ + NKVH), 128>>>(cosb, sinb, qw, kw);
    k_vT<<<dim3(NKVH * HDIM / 32, SQ / 32), dim3(32, 8)>>>();

    // Scores: K-tile resident, 4 q-heads per CTA; then online softmax
    k_scores4<<<dim3(SQ / 128, SQ / 128, NKVH), 256, GSMEM>>>();
    k_softmax<<<dim3(SQ, NHQ), 256>>>();

    // PV: K-chunked partials (balanced) + reduce
    k_pv<<<dim3(4, SQ / 128, NHQ), 256, GSMEM>>>();
    k_pv_reduce<<<(int)((ATTN_N + 255) / 256), 256>>>();

    // Output projection
    k_out<<<dim3(HIDD / 128, SQ / 128), 256, GSMEM>>>(bo, out);

    (void)in_sizes; (void)n_in; (void)out_size;
}

// round 17
// speedup vs baseline: 1.0891x; 1.0891x over previous
#include <cuda_runtime.h>
#include <cstddef>
#include <cstdint>

#define SQ    2048
#define HIDD  2048
#define NHQ   16
#define NKVH  4
#define HDIM  128
#define QKVN  3072
#define QSCALE 0.08838834764831845f
#define RMSEPS 1e-6f

#define ATTN_N ((size_t)SQ * NHQ * HDIM)     // 4.19M elements

// ---------------------------------------------------------------------------
// Scratch (static device globals; allocation is forbidden)
// ---------------------------------------------------------------------------
__device__ float g_qkv   [(size_t)SQ * QKVN];
__device__ float g_q     [(size_t)SQ * NHQ * HDIM];     // tf32-rounded
__device__ float g_k     [(size_t)SQ * NKVH * HDIM];    // tf32-rounded
__device__ float g_vT    [(size_t)NKVH * HDIM * SQ];    // V^T, tf32-rounded
__device__ float g_scores[(size_t)NHQ * SQ * SQ];       // raw scores (fp32)
__device__ float g_attn  [ATTN_N];                      // tf32-rounded
__device__ float g_pvp   [4 * ATTN_N];                  // PV k-chunk partials
__device__ float g_hhi   [(size_t)SQ * HIDD];           // hidden, tf32-rounded
__device__ float g_whi   [(size_t)QKVN * HIDD];         // wqkv, tf32-rounded
__device__ float g_wot   [(size_t)HIDD * HIDD];         // wo tf32-rounded
__device__ float g_rowM  [(size_t)NHQ * SQ];            // softmax row max
__device__ float g_rowI  [(size_t)NHQ * SQ];            // softmax row 1/sum

// ---------------------------------------------------------------------------
// Helpers
// ---------------------------------------------------------------------------
__device__ __forceinline__ float tf32r(float x) {
    unsigned u;
    asm("cvt.rna.tf32.f32 %0, %1;" : "=r"(u) : "f"(x));
    return __uint_as_float(u);
}

__device__ __forceinline__ void cp16(uint32_t dst, const float* src) {
    asm volatile("cp.async.cg.shared.global [%0], [%1], 16;\n" :: "r"(dst), "l"(src));
}

__device__ __forceinline__ void sts128(uint32_t addr, float a, float b,
                                       float c, float d) {
    asm volatile("st.shared.v4.f32 [%0], {%1,%2,%3,%4};"
                 :: "r"(addr), "f"(a), "f"(b), "f"(c), "f"(d));
}

__device__ __forceinline__ void ldm4(uint32_t* r, uint32_t addr) {
    asm volatile("ldmatrix.sync.aligned.m8n8.x4.shared.b16 {%0,%1,%2,%3}, [%4];\n"
                 : "=r"(r[0]), "=r"(r[1]), "=r"(r[2]), "=r"(r[3]) : "r"(addr));
}

__device__ __forceinline__ void mma8(float* c, const uint32_t* a,
                                     uint32_t b0, uint32_t b1) {
    asm volatile(
        "mma.sync.aligned.m16n8k8.row.col.f32.tf32.tf32.f32 "
        "{%0,%1,%2,%3}, {%4,%5,%6,%7}, {%8,%9}, {%0,%1,%2,%3};\n"
        : "+f"(c[0]), "+f"(c[1]), "+f"(c[2]), "+f"(c[3])
        : "r"(a[0]), "r"(a[1]), "r"(a[2]), "r"(a[3]), "r"(b0), "r"(b1));
}

#define SST    36                       // smem row stride (floats)
#define STAGEF (128 * SST)              // floats per matrix per stage
#define CHKB   (STAGEF * 4)             // bytes per 128x32 chunk buffer
#define SSTB   (2 * CHKB)               // bytes per stage (A+B)
#define GSMEM  (3 * SSTB)               // 110592 B
#define PVSMEM (4 * CHKB)               // 73728 B (2 A bufs + 2 B bufs)

// ---------------------------------------------------------------------------
// tf32 GEMM core: C = A * B^T (+bias)(tf32 out), 128x128x32 tiles,
// 3-stage cp.async, single barrier per k-tile.
// ---------------------------------------------------------------------------
__device__ __forceinline__ void cp_stage(const float* Ag, const float* Bg,
                                         int lda, int ldb,
                                         uint32_t dA, uint32_t dB) {
#pragma unroll
    for (int i = 0; i < 4; i++) {
        cp16(dA + i * 32 * SST * 4, Ag + (size_t)(i * 32) * lda);
        cp16(dB + i * 32 * SST * 4, Bg + (size_t)(i * 32) * ldb);
    }
}

__device__ __forceinline__ void gemm_core(
    const float* __restrict__ A, int lda,
    const float* __restrict__ B, int ldb,
    float* __restrict__ C, int ldc,
    int K, const float* __restrict__ bias,
    int cvt, int bx, int by)
{
    extern __shared__ float dsm[];
    const int tid  = threadIdx.x;
    const int wid  = tid >> 5, lane = tid & 31;
    const int wm   = (wid & 1) * 64, wn = (wid >> 1) * 32;
    const int ldrw = tid >> 3, ldcl = (tid & 7) * 4;

    const uint32_t sb = (uint32_t)__cvta_generic_to_shared(dsm);
    const float* Ag = A + (size_t)(by * 128 + ldrw) * lda + ldcl;
    const float* Bg = B + (size_t)(bx * 128 + ldrw) * ldb + ldcl;
    const uint32_t dA0 = sb + (ldrw * SST + ldcl) * 4;

    const int nK = K >> 5;

    float acc[4][4][4];
#pragma unroll
    for (int a = 0; a < 4; a++)
#pragma unroll
        for (int b = 0; b < 4; b++)
#pragma unroll
            for (int c = 0; c < 4; c++) acc[a][b][c] = 0.f;

    const int mi  = lane >> 3, l7 = lane & 7;
    const int aro = (mi & 1) * 8 + l7, aco = (mi >> 1) * 4;
    const int bro = (mi >> 1) * 8 + l7, bco = (mi & 1) * 4;

    cp_stage(Ag, Bg, lda, ldb, dA0, dA0 + CHKB);
    asm volatile("cp.async.commit_group;\n");
    if (nK > 1)
        cp_stage(Ag + 32, Bg + 32, lda, ldb, dA0 + SSTB, dA0 + SSTB + CHKB);
    asm volatile("cp.async.commit_group;\n");

    for (int kt = 0; kt < nK; kt++) {
        asm volatile("cp.async.wait_group 1;\n");
        __syncthreads();

        if (kt + 2 < nK) {
            const int sti = (kt + 2) % 3;
            cp_stage(Ag + (kt + 2) * 32, Bg + (kt + 2) * 32, lda, ldb,
                     dA0 + sti * SSTB, dA0 + sti * SSTB + CHKB);
        }
        asm volatile("cp.async.commit_group;\n");

        const uint32_t sA = sb + (kt % 3) * SSTB;
        const uint32_t sB = sA + CHKB;
#pragma unroll
        for (int k = 0; k < 32; k += 8) {
            uint32_t bq[8];
            ldm4(bq,     sB + ((wn +      bro) * SST + k + bco) * 4);
            ldm4(bq + 4, sB + ((wn + 16 + bro) * SST + k + bco) * 4);
#pragma unroll
            for (int mt = 0; mt < 4; mt++) {
                uint32_t aq[4];
                ldm4(aq, sA + ((wm + 16 * mt + aro) * SST + k + aco) * 4);
                mma8(acc[mt][0], aq, bq[0], bq[1]);
                mma8(acc[mt][1], aq, bq[2], bq[3]);
                mma8(acc[mt][2], aq, bq[4], bq[5]);
                mma8(acc[mt][3], aq, bq[6], bq[7]);
            }
        }
    }

    const int g = lane >> 2, tg = lane & 3;
#pragma unroll
    for (int mt = 0; mt < 4; mt++) {
#pragma unroll
        for (int nt = 0; nt < 4; nt++) {
            const int r0 = by * 128 + wm + 16 * mt + g;
            const int c0 = bx * 128 + wn + 8 * nt + tg * 2;
            float x0 = acc[mt][nt][0], x1 = acc[mt][nt][1];
            float x2 = acc[mt][nt][2], x3 = acc[mt][nt][3];
            if (bias) {
                float b0 = bias[c0], b1 = bias[c0 + 1];
                x0 += b0; x1 += b1; x2 += b0; x3 += b1;
            }
            if (cvt) { x0 = tf32r(x0); x1 = tf32r(x1); x2 = tf32r(x2); x3 = tf32r(x3); }
            *reinterpret_cast<float2*>(C + (size_t)r0 * ldc + c0) = make_float2(x0, x1);
            *reinterpret_cast<float2*>(C + (size_t)(r0 + 8) * ldc + c0) = make_float2(x2, x3);
        }
    }
}

// ---------------------------------------------------------------------------
// GEMM kernels
// ---------------------------------------------------------------------------
__global__ void __launch_bounds__(256, 2) k_qkv(const float* __restrict__ bias) {
    gemm_core(g_hhi, HIDD, g_whi, HIDD, g_qkv, QKVN, HIDD, bias, 0,
              blockIdx.x, blockIdx.y);
}
__global__ void __launch_bounds__(256, 2) k_scores() {
    const int bx = blockIdx.x, by = blockIdx.y, h = blockIdx.z;
    if (bx > by) return;  // entirely above causal diagonal
    gemm_core(g_q + h * HDIM, NHQ * HDIM,
              g_k + (h >> 2) * HDIM, NKVH * HDIM,
              g_scores + (size_t)h * SQ * SQ, SQ, HDIM, nullptr, 0, bx, by);
}
__global__ void __launch_bounds__(256, 2) k_out(const float* __restrict__ bo,
                                                float* __restrict__ out) {
    gemm_core(g_attn, NHQ * HDIM, g_wot, HIDD, out, HIDD, HIDD, bo, 0,
              blockIdx.x, blockIdx.y);
}

// ---------------------------------------------------------------------------
// Fused softmax+PV, split along K into 512-wide chunks -> fp32 partials.
// A operands are RAW scores loaded via LDG, converted in registers:
//   p = (t <= s) ? tf32r(exp(x - M[s]) * inv[s]) : 0
// then STS'd into the swizzled A buffer. B (vT) via cp.async. 2+2 buffers.
// ---------------------------------------------------------------------------
__global__ void __launch_bounds__(256, 2) k_pv_f()
{
    const int x = blockIdx.x, by = blockIdx.y, h = blockIdx.z;
    const int kmax = (by + 1) * 128;
    const int k0 = x * 512;
    if (k0 >= kmax) return;
    const int nK = min(512, kmax - k0) >> 5;

    extern __shared__ float dsm[];
    const int tid  = threadIdx.x;
    const int wid  = tid >> 5, lane = tid & 31;
    const int wm   = (wid & 1) * 64, wn = (wid >> 1) * 32;
    const int ldrw = tid >> 3, ldcl = (tid & 7) * 4;

    const uint32_t sb  = (uint32_t)__cvta_generic_to_shared(dsm);
    const uint32_t dA0 = sb + (ldrw * SST + ldcl) * 4;
    const uint32_t dB0 = sb + 2 * CHKB + (ldrw * SST + ldcl) * 4;

    const float* Ag = g_scores + (size_t)h * SQ * SQ
                    + (size_t)(by * 128 + ldrw) * SQ + k0 + ldcl;
    const float* Bg = g_vT + (size_t)(h >> 2) * HDIM * SQ
                    + (size_t)ldrw * SQ + k0 + ldcl;

    // per-thread row stats (4 A rows)
    float Mr[4], Ir[4]; int sr[4];
#pragma unroll
    for (int i = 0; i < 4; i++) {
        sr[i] = by * 128 + ldrw + 32 * i;
        Mr[i] = g_rowM[h * SQ + sr[i]];
        Ir[i] = g_rowI[h * SQ + sr[i]];
    }

    // prologue: A regs + B cp.async for stage 0
    float4 ar[4];
#pragma unroll
    for (int i = 0; i < 4; i++)
        ar[i] = *reinterpret_cast<const float4*>(Ag + (size_t)(i * 32) * SQ);
#pragma unroll
    for (int i = 0; i < 4; i++)
        cp16(dB0 + i * 32 * SST * 4, Bg + (size_t)(i * 32) * SQ);
    asm volatile("cp.async.commit_group;\n");

    float acc[4][4][4];
#pragma unroll
    for (int a = 0; a < 4; a++)
#pragma unroll
        for (int b = 0; b < 4; b++)
#pragma unroll
            for (int c = 0; c < 4; c++) acc[a][b][c] = 0.f;

    const int mi  = lane >> 3, l7 = lane & 7;
    const int aro = (mi & 1) * 8 + l7, aco = (mi >> 1) * 4;
    const int bro = (mi >> 1) * 8 + l7, bco = (mi & 1) * 4;

    for (int kt = 0; kt < nK; kt++) {
        // transform + store A stage kt into buf[kt&1]
        // (last read at MMA kt-2; ordered by trailing barrier of kt-2)
        const uint32_t dAb = dA0 + (kt & 1) * CHKB;
        const int tb = k0 + kt * 32 + ldcl;
#pragma unroll
        for (int i = 0; i < 4; i++) {
            float p0 = (tb + 0 <= sr[i]) ? tf32r(__expf(ar[i].x - Mr[i]) * Ir[i]) : 0.f;
            float p1 = (tb + 1 <= sr[i]) ? tf32r(__expf(ar[i].y - Mr[i]) * Ir[i]) : 0.f;
            float p2 = (tb + 2 <= sr[i]) ? tf32r(__expf(ar[i].z - Mr[i]) * Ir[i]) : 0.f;
            float p3 = (tb + 3 <= sr[i]) ? tf32r(__expf(ar[i].w - Mr[i]) * Ir[i]) : 0.f;
            sts128(dAb + i * 32 * SST * 4, p0, p1, p2, p3);
        }
        if (kt + 1 < nK) {
#pragma unroll
            for (int i = 0; i < 4; i++)
                ar[i] = *reinterpret_cast<const float4*>(
                    Ag + (size_t)(i * 32) * SQ + (kt + 1) * 32);
#pragma unroll
            for (int i = 0; i < 4; i++)
                cp16(dB0 + ((kt + 1) & 1) * CHKB + i * 32 * SST * 4,
                     Bg + (size_t)(i * 32) * SQ + (kt + 1) * 32);
            asm volatile("cp.async.commit_group;\n");
            asm volatile("cp.async.wait_group 1;\n");
        } else {
            asm volatile("cp.async.wait_group 0;\n");
        }
        __syncthreads();

        const uint32_t sA = sb + (kt & 1) * CHKB;
        const uint32_t sB = sb + 2 * CHKB + (kt & 1) * CHKB;
#pragma unroll
        for (int k = 0; k < 32; k += 8) {
            uint32_t bq[8];
            ldm4(bq,     sB + ((wn +      bro) * SST + k + bco) * 4);
            ldm4(bq + 4, sB + ((wn + 16 + bro) * SST + k + bco) * 4);
#pragma unroll
            for (int mt = 0; mt < 4; mt++) {
                uint32_t aq[4];
                ldm4(aq, sA + ((wm + 16 * mt + aro) * SST + k + aco) * 4);
                mma8(acc[mt][0], aq, bq[0], bq[1]);
                mma8(acc[mt][1], aq, bq[2], bq[3]);
                mma8(acc[mt][2], aq, bq[4], bq[5]);
                mma8(acc[mt][3], aq, bq[6], bq[7]);
            }
        }
        __syncthreads();   // buffers for kt-1 parity free for next prefetch
    }

    // epilogue -> fp32 partials
    float* C = g_pvp + (size_t)x * ATTN_N + h * HDIM;
    const int g = lane >> 2, tg = lane & 3;
#pragma unroll
    for (int mt = 0; mt < 4; mt++) {
#pragma unroll
        for (int nt = 0; nt < 4; nt++) {
            const int r0 = by * 128 + wm + 16 * mt + g;
            const int c0 = wn + 8 * nt + tg * 2;
            *reinterpret_cast<float2*>(C + (size_t)r0 * (NHQ * HDIM) + c0) =
                make_float2(acc[mt][nt][0], acc[mt][nt][1]);
            *reinterpret_cast<float2*>(C + (size_t)(r0 + 8) * (NHQ * HDIM) + c0) =
                make_float2(acc[mt][nt][2], acc[mt][nt][3]);
        }
    }
}

// Sum the per-row chunk count and tf32-round into g_attn
__global__ void __launch_bounds__(256) k_pv_reduce() {
    size_t i = (size_t)blockIdx.x * 256 + threadIdx.x;
    if (i >= ATTN_N) return;
    const int s  = (int)(i >> 11);          // / (NHQ*HDIM)
    const int nc = (s >> 9) + 1;            // chunks covering this row
    float v = g_pvp[i];
    if (nc > 1) v += g_pvp[ATTN_N + i];
    if (nc > 2) v += g_pvp[2 * ATTN_N + i];
    if (nc > 3) v += g_pvp[3 * ATTN_N + i];
    g_attn[i] = tf32r(v);
}

// ---------------------------------------------------------------------------
// Softmax row stats: online max+sum over t<=s; writes M and 1/S only.
// ---------------------------------------------------------------------------
__global__ void __launch_bounds__(256) k_stats()
{
    const int s = blockIdx.x, h = blockIdx.y;
    const float* row = g_scores + ((size_t)h * SQ + s) * SQ;
    const int n = s + 1;
    const int tid = threadIdx.x;
    const int lane = tid & 31, w = tid >> 5;

    float m = -3.4e38f, ssum = 0.f;
    for (int t = tid; t < n; t += 256) {
        float xv = row[t];
        float nm = fmaxf(m, xv);
        ssum = ssum * __expf(m - nm) + __expf(xv - nm);
        m = nm;
    }
#pragma unroll
    for (int o = 16; o; o >>= 1) {
        float om = __shfl_xor_sync(0xffffffffu, m, o);
        float os = __shfl_xor_sync(0xffffffffu, ssum, o);
        float nm = fmaxf(m, om);
        ssum = ssum * __expf(m - nm) + os * __expf(om - nm);
        m = nm;
    }
    __shared__ float sm[8], ss[8];
    if (lane == 0) { sm[w] = m; ss[w] = ssum; }
    __syncthreads();
    if (tid == 0) {
        float M = sm[0], S = ss[0];
#pragma unroll
        for (int i = 1; i < 8; i++) {
            float nm = fmaxf(M, sm[i]);
            S = S * __expf(M - nm) + ss[i] * __expf(sm[i] - nm);
            M = nm;
        }
        g_rowM[h * SQ + s] = M;
        g_rowI[h * SQ + s] = 1.0f / S;
    }
}

// ---------------------------------------------------------------------------
// tf32 prep kernels
// ---------------------------------------------------------------------------
__global__ void __launch_bounds__(256) k_round_h(const float* __restrict__ x) {
    int i = blockIdx.x * 256 + threadIdx.x;
    if (i < SQ * HIDD) g_hhi[i] = tf32r(x[i]);
}
__global__ void __launch_bounds__(256) k_cvt_w(const float* __restrict__ x) {
    int i = blockIdx.x * 256 + threadIdx.x;
    if (i < QKVN * HIDD) g_whi[i] = tf32r(x[i]);
}
__global__ void __launch_bounds__(256) k_cvt_wo(const float* __restrict__ x) {
    int i = blockIdx.x * 256 + threadIdx.x;
    if (i < HIDD * HIDD) g_wot[i] = tf32r(x[i]);
}

// V transpose: g_vT[c][s] = tf32(g_qkv[s][2560 + c]),  c in [0, 512)
__global__ void __launch_bounds__(256) k_vT() {
    __shared__ float t[32][33];
    const int c0 = blockIdx.x * 32, s0 = blockIdx.y * 32;
    const int tx = threadIdx.x, ty = threadIdx.y;  // 32 x 8
#pragma unroll
    for (int j = 0; j < 32; j += 8)
        t[ty + j][tx] = g_qkv[(size_t)(s0 + ty + j) * QKVN
                              + (NHQ + NKVH) * HDIM + c0 + tx];
    __syncthreads();
#pragma unroll
    for (int j = 0; j < 32; j += 8)
        g_vT[(size_t)(c0 + ty + j) * SQ + s0 + tx] = tf32r(t[tx][ty + j]);
}

// ---------------------------------------------------------------------------
// RMSNorm + RoPE (+q scaling), outputs tf32-rounded. grid (S, 20), 128 thr.
// ---------------------------------------------------------------------------
__global__ void __launch_bounds__(128) k_norm_rope(
    const float* __restrict__ cosb, const float* __restrict__ sinb,
    const float* __restrict__ qw,   const float* __restrict__ kw)
{
    const int s  = blockIdx.x;
    const int hh = blockIdx.y;
    const int d  = threadIdx.x;
    const float* row = g_qkv + (size_t)s * QKVN;

    const bool isq = (hh < 16);
    const int off = isq ? hh * HDIM : NHQ * HDIM + (hh - 16) * HDIM;
    float x = row[off + d];

    float sq = x * x;
#pragma unroll
    for (int o = 16; o; o >>= 1) sq += __shfl_xor_sync(0xffffffffu, sq, o);
    __shared__ float ws[4];
    __shared__ float rinv;
    if ((d & 31) == 0) ws[d >> 5] = sq;
    __syncthreads();
    if (d == 0)
        rinv = rsqrtf((ws[0] + ws[1] + ws[2] + ws[3]) * (1.0f / 128.0f) + RMSEPS);
    __syncthreads();

    const float w = isq ? qw[d] : kw[d];
    float xn = x * rinv * w;

    __shared__ float xs[128];
    xs[d] = xn;
    __syncthreads();

    const int j = d & 63;
    const float c  = cosb[(size_t)s * 64 + j];
    const float sn = sinb[(size_t)s * 64 + j];
    float o;
    if (d < 64) o = xs[d] * c - xs[d + 64] * sn;
    else        o = xs[j] * sn + xs[j + 64] * c;

    if (isq)
        g_q[(size_t)s * (NHQ * HDIM) + hh * HDIM + d] = tf32r(o * QSCALE);
    else
        g_k[(size_t)s * (NKVH * HDIM) + (hh - 16) * HDIM + d] = tf32r(o);
}

// ---------------------------------------------------------------------------
// Launch
// ---------------------------------------------------------------------------
extern "C" void kernel_launch(void* const* d_in, const int* in_sizes, int n_in,
                              void* d_out, int out_size)
{
    const float* hidden = (const float*)d_in[0];
    const float* cosb   = (const float*)d_in[1];
    const float* sinb   = (const float*)d_in[2];
    const float* wqkv   = (const float*)d_in[6];
    const float* bqkv   = (const float*)d_in[7];
    const float* wo     = (const float*)d_in[8];
    const float* bo     = (const float*)d_in[9];
    const float* qw     = (const float*)d_in[10];
    const float* kw     = (const float*)d_in[11];
    float* out = (float*)d_out;

    cudaFuncSetAttribute(k_qkv,    cudaFuncAttributeMaxDynamicSharedMemorySize, GSMEM);
    cudaFuncSetAttribute(k_scores, cudaFuncAttributeMaxDynamicSharedMemorySize, GSMEM);
    cudaFuncSetAttribute(k_pv_f,   cudaFuncAttributeMaxDynamicSharedMemorySize, PVSMEM);
    cudaFuncSetAttribute(k_out,    cudaFuncAttributeMaxDynamicSharedMemorySize, GSMEM);

    // tf32 prep (single-rounded operands)
    k_round_h<<<(SQ * HIDD + 255) / 256, 256>>>(hidden);
    k_cvt_w<<<(QKVN * HIDD + 255) / 256, 256>>>(wqkv);
    k_cvt_wo<<<(HIDD * HIDD + 255) / 256, 256>>>(wo);

    // QKV single-pass tf32 GEMM
    k_qkv<<<dim3(QKVN / 128, SQ / 128), 256, GSMEM>>>(bqkv);

    // RMSNorm + RoPE (+scale) -> tf32 q/k; V transposed -> tf32 vT
    k_norm_rope<<<dim3(SQ, NHQ + NKVH), 128>>>(cosb, sinb, qw, kw);
    k_vT<<<dim3(NKVH * HDIM / 32, SQ / 32), dim3(32, 8)>>>();

    // Scores (causal tile skip) -> raw scores; row stats only
    k_scores<<<dim3(SQ / 128, SQ / 128, NHQ), 256, GSMEM>>>();
    k_stats<<<dim3(SQ, NHQ), 256>>>();

    // Fused softmax+PV split-K partials + reduce
    k_pv_f<<<dim3(4, SQ / 128, NHQ), 256, PVSMEM>>>();
    k_pv_reduce<<<(int)((ATTN_N + 255) / 256), 256>>>();

    // Output projection
    k_out<<<dim3(HIDD / 128, SQ / 128), 256, GSMEM>>>(bo, out);

    (void)in_sizes; (void)n_in; (void)out_size;
}